// round 6
// baseline (speedup 1.0000x reference)
#include <cuda_runtime.h>
#include <cstdint>

#define NB 4
#define NN 4096
#define FF 256
#define HH 256
#define EE 262144
#define NTOT 16384
#define EP (EE + NTOT)
#define LL 3

// ---------------- scratch (static device memory; no allocation) ----------------
__device__ __align__(16) float g_xpad[NB * (NN + 2) * FF];   // padded x, [B, N+2, F]
__device__ __align__(16) float g_Wb[768 * 256];              // conv weight as [K=768, N=256]
__device__ __align__(16) float g_h0[NTOT * HH];
__device__ __align__(16) float g_h1[NTOT * HH];
__device__ __align__(16) float g_hw[NTOT * HH];
__device__ float g_s[NTOT];
__device__ float g_d[NTOT];
__device__ int   g_deg[NTOT];
__device__ int   g_off[NTOT + 1];
__device__ int   g_cur[NTOT];
__device__ int   g_csrc[EP];

// ---------------- build padded x (float4 granularity) ----------------
__global__ void k_xpad(const float* __restrict__ x) {
    int idx = blockIdx.x * 256 + threadIdx.x;       // over NB*4098*64 float4s
    if (idx >= NB * 4098 * 64) return;
    int c4 = idx & 63;
    int m  = (idx >> 6) % 4098;
    int b  = idx / (4098 * 64);
    float4 v = make_float4(0.f, 0.f, 0.f, 0.f);
    if (m >= 1 && m <= 4096)
        v = ((const float4*)x)[(b * 4096 + (m - 1)) * 64 + c4];
    ((float4*)g_xpad)[idx] = v;
}

// Wb[(k*256 + c)*256 + o] = tc_w[o][c][k]   (tc_w is [H,F,3] row-major)
__global__ void k_wb(const float* __restrict__ tc_w) {
    int idx = blockIdx.x * 256 + threadIdx.x;       // 768*256
    int o = idx & 255;
    int r = idx >> 8;
    int c = r & 255;
    int k = r >> 8;
    g_Wb[idx] = tc_w[o * 768 + c * 3 + k];
}

// ---------------- CSR build (by dst, self-loops included); edge_index is int32 ----------------
__global__ void k_deg_init() {
    int i = blockIdx.x * 256 + threadIdx.x;
    if (i < NTOT) g_deg[i] = 1;                     // self loop
}
__global__ void k_deg_count(const int* __restrict__ ei) {
    int e = blockIdx.x * 256 + threadIdx.x;
    if (e < EE) atomicAdd(&g_deg[ei[EE + e]], 1);
}
__global__ void k_scan() {
    __shared__ int ssum[1024];
    int t = threadIdx.x;
    int v[16]; int tot = 0;
#pragma unroll
    for (int i = 0; i < 16; i++) { v[i] = g_deg[t * 16 + i]; tot += v[i]; }
    ssum[t] = tot;
    __syncthreads();
    for (int off = 1; off < 1024; off <<= 1) {
        int xv = (t >= off) ? ssum[t - off] : 0;
        __syncthreads();
        ssum[t] += xv;
        __syncthreads();
    }
    int pre = (t == 0) ? 0 : ssum[t - 1];
#pragma unroll
    for (int i = 0; i < 16; i++) {
        g_off[t * 16 + i] = pre;
        g_cur[t * 16 + i] = pre;
        pre += v[i];
    }
    if (t == 1023) g_off[NTOT] = ssum[1023];
}
__global__ void k_fill(const int* __restrict__ ei) {
    int idx = blockIdx.x * 256 + threadIdx.x;
    if (idx < NTOT) {
        int pos = atomicAdd(&g_cur[idx], 1);
        g_csrc[pos] = idx;                           // self loop
    } else if (idx < NTOT + EE) {
        int e   = idx - NTOT;
        int src = ei[e];
        int dst = ei[EE + e];
        int pos = atomicAdd(&g_cur[dst], 1);
        g_csrc[pos] = src;
    }
}

// ---------------- tf32 MMA GEMM, double-buffered + register prefetch ----------------
// 128x128x32 CTA tile, 8 warps, 64x32 warp tile, one __syncthreads per K-tile.
#define AS_STRIDE 36    // 32 + 4 pad: A-frag lds banks = 4*gid+tig (conflict-free)
#define BS_STRIDE 136   // 128 + 8 pad: B-frag lds banks = 8*tig+gid (conflict-free)
#define AS_BUF (128 * AS_STRIDE)   // 4608 floats
#define BS_BUF (32 * BS_STRIDE)    // 4352 floats
#define MMA_SMEM_BYTES ((2 * AS_BUF + 2 * BS_BUF) * 4)   // 71680 B

__device__ __forceinline__ float4 cvt4_tf32(float4 v) {
    uint32_t u0, u1, u2, u3;
    asm("cvt.rna.tf32.f32 %0, %1;" : "=r"(u0) : "f"(v.x));
    asm("cvt.rna.tf32.f32 %0, %1;" : "=r"(u1) : "f"(v.y));
    asm("cvt.rna.tf32.f32 %0, %1;" : "=r"(u2) : "f"(v.z));
    asm("cvt.rna.tf32.f32 %0, %1;" : "=r"(u3) : "f"(v.w));
    return make_float4(__uint_as_float(u0), __uint_as_float(u1),
                       __uint_as_float(u2), __uint_as_float(u3));
}

template <bool CONV>
__global__ __launch_bounds__(256)
void k_mma(const float* __restrict__ Bext, int flip,
           const float* __restrict__ bias, const float* __restrict__ resid) {
    const float* A  = CONV ? g_xpad : (flip ? g_h1 : g_h0);
    const float* Bg = CONV ? g_Wb : Bext;
    float* C        = CONV ? g_h0 : g_hw;
    const int T     = CONV ? 24 : 8;        // K/32 tiles

    extern __shared__ __align__(16) float smem[];
    float* Asm = smem;                      // 2 buffers of AS_BUF
    float* Bsm = smem + 2 * AS_BUF;         // 2 buffers of BS_BUF

    int tid  = threadIdx.x;
    int wid  = tid >> 5, lane = tid & 31;
    int gid  = lane >> 2, tig = lane & 3;
    int wm   = (wid >> 2) * 64;
    int wn   = (wid & 3) * 32;
    int bm   = blockIdx.y * 128, bn = blockIdx.x * 128;

    float acc[4][4][4];
#pragma unroll
    for (int mt = 0; mt < 4; mt++)
#pragma unroll
        for (int nt = 0; nt < 4; nt++)
#pragma unroll
            for (int r = 0; r < 4; r++) acc[mt][nt][r] = 0.f;

    float4 pa[4], pb[4];

    // ---- prologue: load tile 0, stage into buffer 0 ----
#pragma unroll
    for (int i = 0; i < 4; i++) {
        int idx = tid + i * 256;
        int r = idx >> 3, c4 = idx & 7;
        int row = bm + r;
        int off = CONV ? row * 256 + (row >> 12) * 512 + c4 * 4
                       : row * 256 + c4 * 4;
        pa[i] = *(const float4*)(A + off);
        int rb = idx >> 5, cb = idx & 31;
        pb[i] = *(const float4*)(Bg + rb * 256 + bn + cb * 4);
    }
#pragma unroll
    for (int i = 0; i < 4; i++) {
        int idx = tid + i * 256;
        int r = idx >> 3, c4 = idx & 7;
        *(float4*)&Asm[r * AS_STRIDE + c4 * 4] = cvt4_tf32(pa[i]);
        int rb = idx >> 5, cb = idx & 31;
        *(float4*)&Bsm[rb * BS_STRIDE + cb * 4] = cvt4_tf32(pb[i]);
    }
    __syncthreads();

    for (int t = 0; t < T; t++) {
        int buf = t & 1;
        const float* As = Asm + buf * AS_BUF;
        const float* Bs = Bsm + buf * BS_BUF;

        // ---- issue global loads for tile t+1 (latency hidden by compute) ----
        if (t + 1 < T) {
            int k0 = (t + 1) * 32;
#pragma unroll
            for (int i = 0; i < 4; i++) {
                int idx = tid + i * 256;
                int r = idx >> 3, c4 = idx & 7;
                int row = bm + r;
                int off = CONV ? row * 256 + (row >> 12) * 512 + k0 + c4 * 4
                               : row * 256 + k0 + c4 * 4;
                pa[i] = *(const float4*)(A + off);
                int rb = idx >> 5, cb = idx & 31;
                pb[i] = *(const float4*)(Bg + (k0 + rb) * 256 + bn + cb * 4);
            }
        }

        // ---- compute on current buffer ----
#pragma unroll
        for (int ks = 0; ks < 4; ks++) {
            int kk = ks * 8;
            uint32_t af[4][4], bf[4][2];
#pragma unroll
            for (int mt = 0; mt < 4; mt++) {
                int r0 = wm + mt * 16;
                af[mt][0] = __float_as_uint(As[(r0 + gid)     * AS_STRIDE + kk + tig]);
                af[mt][1] = __float_as_uint(As[(r0 + gid + 8) * AS_STRIDE + kk + tig]);
                af[mt][2] = __float_as_uint(As[(r0 + gid)     * AS_STRIDE + kk + tig + 4]);
                af[mt][3] = __float_as_uint(As[(r0 + gid + 8) * AS_STRIDE + kk + tig + 4]);
            }
#pragma unroll
            for (int nt = 0; nt < 4; nt++) {
                int c0 = wn + nt * 8;
                bf[nt][0] = __float_as_uint(Bs[(kk + tig)     * BS_STRIDE + c0 + gid]);
                bf[nt][1] = __float_as_uint(Bs[(kk + tig + 4) * BS_STRIDE + c0 + gid]);
            }
#pragma unroll
            for (int mt = 0; mt < 4; mt++)
#pragma unroll
                for (int nt = 0; nt < 4; nt++)
                    asm volatile(
                        "mma.sync.aligned.m16n8k8.row.col.f32.tf32.tf32.f32 "
                        "{%0,%1,%2,%3}, {%4,%5,%6,%7}, {%8,%9}, {%0,%1,%2,%3};"
                        : "+f"(acc[mt][nt][0]), "+f"(acc[mt][nt][1]),
                          "+f"(acc[mt][nt][2]), "+f"(acc[mt][nt][3])
                        : "r"(af[mt][0]), "r"(af[mt][1]), "r"(af[mt][2]), "r"(af[mt][3]),
                          "r"(bf[nt][0]), "r"(bf[nt][1]));
        }

        // ---- stage tile t+1 into the other buffer ----
        if (t + 1 < T) {
            float* Asn = Asm + (buf ^ 1) * AS_BUF;
            float* Bsn = Bsm + (buf ^ 1) * BS_BUF;
#pragma unroll
            for (int i = 0; i < 4; i++) {
                int idx = tid + i * 256;
                int r = idx >> 3, c4 = idx & 7;
                *(float4*)&Asn[r * AS_STRIDE + c4 * 4] = cvt4_tf32(pa[i]);
                int rb = idx >> 5, cb = idx & 31;
                *(float4*)&Bsn[rb * BS_STRIDE + cb * 4] = cvt4_tf32(pb[i]);
            }
        }
        __syncthreads();
    }

    // epilogue: c0,c1 at (row, col..col+1); c2,c3 at (row+8, col..col+1)
#pragma unroll
    for (int mt = 0; mt < 4; mt++) {
#pragma unroll
        for (int nt = 0; nt < 4; nt++) {
            int row0 = bm + wm + mt * 16 + gid;
            int row1 = row0 + 8;
            int col  = bn + wn + nt * 8 + tig * 2;
            float2 v0 = make_float2(acc[mt][nt][0], acc[mt][nt][1]);
            float2 v1 = make_float2(acc[mt][nt][2], acc[mt][nt][3]);
            if (CONV) {
                float2 b2 = *(const float2*)(bias + col);
                float2 r0 = *(const float2*)(resid + row0 * 256 + col);
                float2 r1 = *(const float2*)(resid + row1 * 256 + col);
                v0.x = fmaxf(v0.x + b2.x + r0.x, 0.f);
                v0.y = fmaxf(v0.y + b2.y + r0.y, 0.f);
                v1.x = fmaxf(v1.x + b2.x + r1.x, 0.f);
                v1.y = fmaxf(v1.y + b2.y + r1.y, 0.f);
            }
            *(float2*)(C + row0 * 256 + col) = v0;
            *(float2*)(C + row1 * 256 + col) = v1;
        }
    }
}

// ---------------- per-node attention scalars: s_i = hw_i . a_s ; d_i = hw_i . a_d ----------------
__global__ void k_scalars(const float* __restrict__ a_s, const float* __restrict__ a_d) {
    int w = (blockIdx.x * 256 + threadIdx.x) >> 5;
    int lane = threadIdx.x & 31;
    if (w >= NTOT) return;
    const float4* r  = (const float4*)g_hw + w * 64;
    const float4* s4 = (const float4*)a_s;
    const float4* d4 = (const float4*)a_d;
    float4 v0 = r[lane], v1 = r[lane + 32];
    float4 sa = s4[lane], sb = s4[lane + 32];
    float4 da = d4[lane], db = d4[lane + 32];
    float ss = v0.x * sa.x + v0.y * sa.y + v0.z * sa.z + v0.w * sa.w
             + v1.x * sb.x + v1.y * sb.y + v1.z * sb.z + v1.w * sb.w;
    float dd = v0.x * da.x + v0.y * da.y + v0.z * da.z + v0.w * da.w
             + v1.x * db.x + v1.y * db.y + v1.z * db.z + v1.w * db.w;
#pragma unroll
    for (int o = 16; o; o >>= 1) {
        ss += __shfl_xor_sync(0xFFFFFFFFu, ss, o);
        dd += __shfl_xor_sync(0xFFFFFFFFu, dd, o);
    }
    if (lane == 0) { g_s[w] = ss; g_d[w] = dd; }
}

// ---------------- fused edge softmax + aggregate: one warp per dst node ----------------
__global__ __launch_bounds__(256)
void k_gat_edges(const float* __restrict__ bias, int flip) {
    float* hout = flip ? g_h0 : g_h1;
    int w = (blockIdx.x * 256 + threadIdx.x) >> 5;
    int lane = threadIdx.x & 31;
    if (w >= NTOT) return;
    int beg = g_off[w], end = g_off[w + 1];
    float dj = g_d[w];

    float mx = -1e30f;
    for (int i = beg + lane; i < end; i += 32) {
        float e = g_s[g_csrc[i]] + dj;
        e = e > 0.f ? e : 0.2f * e;
        mx = fmaxf(mx, e);
    }
#pragma unroll
    for (int o = 16; o; o >>= 1) mx = fmaxf(mx, __shfl_xor_sync(0xFFFFFFFFu, mx, o));

    float sum = 0.f;
    for (int i = beg + lane; i < end; i += 32) {
        float e = g_s[g_csrc[i]] + dj;
        e = e > 0.f ? e : 0.2f * e;
        sum += __expf(e - mx);
    }
#pragma unroll
    for (int o = 16; o; o >>= 1) sum += __shfl_xor_sync(0xFFFFFFFFu, sum, o);
    float inv = 1.f / sum;

    float4 acc0 = make_float4(0.f, 0.f, 0.f, 0.f);
    float4 acc1 = make_float4(0.f, 0.f, 0.f, 0.f);
    const float4* hw4 = (const float4*)g_hw;
    for (int i = beg; i < end; i++) {
        int s_ = g_csrc[i];                  // uniform across the warp
        float e = g_s[s_] + dj;
        e = e > 0.f ? e : 0.2f * e;
        float wt = __expf(e - mx) * inv;
        const float4* r = hw4 + s_ * 64;
        float4 v0 = r[lane], v1 = r[lane + 32];
        acc0.x += wt * v0.x; acc0.y += wt * v0.y; acc0.z += wt * v0.z; acc0.w += wt * v0.w;
        acc1.x += wt * v1.x; acc1.y += wt * v1.y; acc1.z += wt * v1.z; acc1.w += wt * v1.w;
    }
    const float4* b4 = (const float4*)bias;
    float4 bb0 = b4[lane], bb1 = b4[lane + 32];
    float4 o0, o1;
    o0.x = fmaxf(acc0.x + bb0.x, 0.f); o0.y = fmaxf(acc0.y + bb0.y, 0.f);
    o0.z = fmaxf(acc0.z + bb0.z, 0.f); o0.w = fmaxf(acc0.w + bb0.w, 0.f);
    o1.x = fmaxf(acc1.x + bb1.x, 0.f); o1.y = fmaxf(acc1.y + bb1.y, 0.f);
    o1.z = fmaxf(acc1.z + bb1.z, 0.f); o1.w = fmaxf(acc1.w + bb1.w, 0.f);
    ((float4*)hout)[w * 64 + lane]      = o0;
    ((float4*)hout)[w * 64 + 32 + lane] = o1;
}

// ---------------- final conv (position 0 only) + LayerNorm + relu ----------------
__global__ void k_final(const float* __restrict__ tc_w,
                        const float* __restrict__ tc_b, const float* __restrict__ ln_g,
                        const float* __restrict__ ln_b, float* __restrict__ out) {
    __shared__ float h0s[256], h1s[256], red[256];
    int b = blockIdx.x, t = threadIdx.x;
    h0s[t] = g_h1[(b * NN + 0) * 256 + t];
    h1s[t] = g_h1[(b * NN + 1) * 256 + t];
    __syncthreads();
    float v = tc_b[t];
    const float* wr = tc_w + t * 768;
    for (int c = 0; c < 256; c++)
        v += wr[c * 3 + 1] * h0s[c] + wr[c * 3 + 2] * h1s[c];
    red[t] = v;
    __syncthreads();
    for (int o = 128; o; o >>= 1) { if (t < o) red[t] += red[t + o]; __syncthreads(); }
    float mu = red[0] / 256.f;
    __syncthreads();
    red[t] = (v - mu) * (v - mu);
    __syncthreads();
    for (int o = 128; o; o >>= 1) { if (t < o) red[t] += red[t + o]; __syncthreads(); }
    float var = red[0] / 256.f;
    float rs = rsqrtf(var + 1e-5f);
    out[b * 256 + t] = fmaxf((v - mu) * rs * ln_g[t] + ln_b[t], 0.f);
}

// ---------------- launch ----------------
extern "C" void kernel_launch(void* const* d_in, const int* in_sizes, int n_in,
                              void* d_out, int out_size) {
    (void)in_sizes; (void)n_in; (void)out_size;
    const float* x      = (const float*)d_in[0];
    const int*   ei     = (const int*)d_in[1];        // int32 edge_index [2, E]
    const float* tc_w   = (const float*)d_in[2];
    const float* tc_b   = (const float*)d_in[3];
    const float* gat_W  = (const float*)d_in[4];
    const float* gat_as = (const float*)d_in[5];
    const float* gat_ad = (const float*)d_in[6];
    const float* gat_b  = (const float*)d_in[7];
    const float* ln_g   = (const float*)d_in[8];
    const float* ln_b   = (const float*)d_in[9];
    float* out = (float*)d_out;

    // opt-in to >48KB dynamic smem for the MMA kernels (idempotent, not an alloc)
    cudaFuncSetAttribute(k_mma<true>,  cudaFuncAttributeMaxDynamicSharedMemorySize, MMA_SMEM_BYTES);
    cudaFuncSetAttribute(k_mma<false>, cudaFuncAttributeMaxDynamicSharedMemorySize, MMA_SMEM_BYTES);

    // input prep + CSR build
    k_xpad<<<(NB * 4098 * 64 + 255) / 256, 256>>>(x);
    k_wb<<<768, 256>>>(tc_w);
    k_deg_init<<<(NTOT + 255) / 256, 256>>>();
    k_deg_count<<<EE / 256, 256>>>(ei);
    k_scan<<<1, 1024>>>();
    k_fill<<<(EP + 255) / 256, 256>>>(ei);

    // temporal conv (as GEMM M=16384, N=256, K=768) + residual + relu -> g_h0
    k_mma<true><<<dim3(2, 128), 256, MMA_SMEM_BYTES>>>(nullptr, 0, tc_b, x);

    // 3 GAT layers (ping-pong g_h0 <-> g_h1 via flip flag)
    for (int l = 0; l < LL; l++) {
        int flip = l & 1;
        k_mma<false><<<dim3(2, 128), 256, MMA_SMEM_BYTES>>>(gat_W + l * 256 * 256, flip, nullptr, nullptr);
        k_scalars<<<(NTOT * 32 + 255) / 256, 256>>>(gat_as + l * 256, gat_ad + l * 256);
        k_gat_edges<<<(NTOT * 32 + 255) / 256, 256>>>(gat_b + l * 256, flip);
    }

    // final conv at n=0 + layernorm + relu (reads g_h1)
    k_final<<<NB, 256>>>(tc_w, tc_b, ln_g, ln_b, out);
}

// round 7
// speedup vs baseline: 1.0484x; 1.0484x over previous
#include <cuda_runtime.h>
#include <cstdint>

#define NB 4
#define NN 4096
#define FF 256
#define HH 256
#define EE 262144
#define NTOT 16384
#define EP (EE + NTOT)
#define LL 3

// ---------------- scratch (static device memory; no allocation) ----------------
__device__ __align__(16) float g_xpad[NB * (NN + 2) * FF];   // padded x (tf32-rounded)
__device__ __align__(16) float g_Wb[768 * 256];              // conv weight [K,N] (tf32-rounded)
__device__ __align__(16) float g_Wl[LL * 256 * 256];         // gat_W rounded copies
__device__ __align__(16) float g_h0[NTOT * HH];
__device__ __align__(16) float g_h1[NTOT * HH];
__device__ __align__(16) float g_hw[NTOT * HH];
__device__ float g_s[NTOT];
__device__ float g_d[NTOT];
__device__ int   g_deg[NTOT];
__device__ int   g_off[NTOT + 1];
__device__ int   g_cur[NTOT];
__device__ int   g_csrc[EP];

__device__ __forceinline__ float cvt_tf32(float x) {
    uint32_t u;
    asm("cvt.rna.tf32.f32 %0, %1;" : "=r"(u) : "f"(x));
    return __uint_as_float(u);
}
__device__ __forceinline__ float4 cvt4_tf32(float4 v) {
    return make_float4(cvt_tf32(v.x), cvt_tf32(v.y), cvt_tf32(v.z), cvt_tf32(v.w));
}

// ---------------- build padded x (tf32-rounded) ----------------
__global__ void k_xpad(const float* __restrict__ x) {
    int idx = blockIdx.x * 256 + threadIdx.x;       // over NB*4098*64 float4s
    if (idx >= NB * 4098 * 64) return;
    int c4 = idx & 63;
    int m  = (idx >> 6) % 4098;
    int b  = idx / (4098 * 64);
    float4 v = make_float4(0.f, 0.f, 0.f, 0.f);
    if (m >= 1 && m <= 4096)
        v = cvt4_tf32(((const float4*)x)[(b * 4096 + (m - 1)) * 64 + c4]);
    ((float4*)g_xpad)[idx] = v;
}

// Wb[(k*256 + c)*256 + o] = tc_w[o][c][k]  (rounded)
__global__ void k_wb(const float* __restrict__ tc_w) {
    int idx = blockIdx.x * 256 + threadIdx.x;       // 768*256
    int o = idx & 255;
    int r = idx >> 8;
    int c = r & 255;
    int k = r >> 8;
    g_Wb[idx] = cvt_tf32(tc_w[o * 768 + c * 3 + k]);
}

// rounded copy of gat_W (already [K=in, N=out] row-major per layer)
__global__ void k_wl(const float* __restrict__ gat_W) {
    int idx = blockIdx.x * 256 + threadIdx.x;       // LL*256*256
    g_Wl[idx] = cvt_tf32(gat_W[idx]);
}

// ---------------- CSR build (by dst, self-loops included); edge_index is int32 ----------------
__global__ void k_deg_init() {
    int i = blockIdx.x * 256 + threadIdx.x;
    if (i < NTOT) g_deg[i] = 1;                     // self loop
}
__global__ void k_deg_count(const int* __restrict__ ei) {
    int e = blockIdx.x * 256 + threadIdx.x;
    if (e < EE) atomicAdd(&g_deg[ei[EE + e]], 1);
}
__global__ void k_scan() {
    __shared__ int ssum[1024];
    int t = threadIdx.x;
    int v[16]; int tot = 0;
#pragma unroll
    for (int i = 0; i < 16; i++) { v[i] = g_deg[t * 16 + i]; tot += v[i]; }
    ssum[t] = tot;
    __syncthreads();
    for (int off = 1; off < 1024; off <<= 1) {
        int xv = (t >= off) ? ssum[t - off] : 0;
        __syncthreads();
        ssum[t] += xv;
        __syncthreads();
    }
    int pre = (t == 0) ? 0 : ssum[t - 1];
#pragma unroll
    for (int i = 0; i < 16; i++) {
        g_off[t * 16 + i] = pre;
        g_cur[t * 16 + i] = pre;
        pre += v[i];
    }
    if (t == 1023) g_off[NTOT] = ssum[1023];
}
__global__ void k_fill(const int* __restrict__ ei) {
    int idx = blockIdx.x * 256 + threadIdx.x;
    if (idx < NTOT) {
        int pos = atomicAdd(&g_cur[idx], 1);
        g_csrc[pos] = idx;                           // self loop
    } else if (idx < NTOT + EE) {
        int e   = idx - NTOT;
        int src = ei[e];
        int dst = ei[EE + e];
        int pos = atomicAdd(&g_cur[dst], 1);
        g_csrc[pos] = src;
    }
}

// ---------------- tf32 MMA GEMM: cp.async 2-stage, 128x128x32, 8 warps ----------------
#define AS_STRIDE 36    // 32 + 4 pad: A-frag lds banks = 4*gid+tig (conflict-free)
#define BS_STRIDE 136   // 128 + 8 pad: B-frag lds banks = 8*tig+gid (conflict-free)
#define AS_BUF (128 * AS_STRIDE)   // 4608 floats
#define BS_BUF (32 * BS_STRIDE)    // 4352 floats
#define MMA_SMEM_BYTES ((2 * AS_BUF + 2 * BS_BUF) * 4)   // 71680 B

__device__ __forceinline__ void cp_async16(uint32_t saddr, const void* gptr) {
    asm volatile("cp.async.cg.shared.global [%0], [%1], 16;\n" :: "r"(saddr), "l"(gptr));
}

// LAYER: -1 = conv (A=g_xpad, B=g_Wb, K=768, epilogue), 0..2 = GAT layer (B=g_Wl+l*65536)
template <int LAYER>
__global__ __launch_bounds__(256, 2)
void k_mma(int flip, const float* __restrict__ bias, const float* __restrict__ resid) {
    constexpr bool CONV = (LAYER < 0);
    const float* A  = CONV ? g_xpad : (flip ? g_h1 : g_h0);
    const float* Bg = CONV ? g_Wb : g_Wl + (LAYER < 0 ? 0 : LAYER) * 65536;
    float* C        = CONV ? g_h0 : g_hw;
    const int T     = CONV ? 24 : 8;        // K/32 tiles

    extern __shared__ __align__(16) float smem[];
    float* Asm = smem;
    float* Bsm = smem + 2 * AS_BUF;
    uint32_t sA = (uint32_t)__cvta_generic_to_shared(Asm);
    uint32_t sB = (uint32_t)__cvta_generic_to_shared(Bsm);

    int tid  = threadIdx.x;
    int wid  = tid >> 5, lane = tid & 31;
    int gid  = lane >> 2, tig = lane & 3;
    int wm   = (wid >> 2) * 64;
    int wn   = (wid & 3) * 32;
    int bm   = blockIdx.y * 128, bn = blockIdx.x * 128;

    // per-thread staging coordinates (4 float4s each for A and B per tile)
    int raw = tid >> 3;          // A rows: idx>>3 for idx = tid + i*256 -> raw + i*32
    int caw = (tid & 7) * 4;
    int rbw = tid >> 5;          // B rows: rbw + i*8
    int cbw = (tid & 31) * 4;

    float acc[4][4][4];
#pragma unroll
    for (int mt = 0; mt < 4; mt++)
#pragma unroll
        for (int nt = 0; nt < 4; nt++)
#pragma unroll
            for (int r = 0; r < 4; r++) acc[mt][nt][r] = 0.f;

    // prologue: stage tile 0 into buffer 0
#pragma unroll
    for (int i = 0; i < 4; i++) {
        int r = raw + i * 32;
        int row = bm + r;
        const float* ga = A + (CONV ? row * 256 + (row >> 12) * 512 + caw
                                    : row * 256 + caw);
        cp_async16(sA + (r * AS_STRIDE + caw) * 4, ga);
        int rb = rbw + i * 8;
        cp_async16(sB + (rb * BS_STRIDE + cbw) * 4, Bg + rb * 256 + bn + cbw);
    }
    asm volatile("cp.async.commit_group;\n");

    for (int t = 0; t < T; t++) {
        int buf = t & 1;
        if (t + 1 < T) {
            int k0 = (t + 1) * 32;
            uint32_t dA = sA + ((buf ^ 1) * AS_BUF) * 4;
            uint32_t dB = sB + ((buf ^ 1) * BS_BUF) * 4;
#pragma unroll
            for (int i = 0; i < 4; i++) {
                int r = raw + i * 32;
                int row = bm + r;
                const float* ga = A + (CONV ? row * 256 + (row >> 12) * 512 + k0 + caw
                                            : row * 256 + k0 + caw);
                cp_async16(dA + (r * AS_STRIDE + caw) * 4, ga);
                int rb = rbw + i * 8;
                cp_async16(dB + (rb * BS_STRIDE + cbw) * 4, Bg + (k0 + rb) * 256 + bn + cbw);
            }
            asm volatile("cp.async.commit_group;\n");
            asm volatile("cp.async.wait_group 1;\n");
        } else {
            asm volatile("cp.async.wait_group 0;\n");
        }
        __syncthreads();

        const float* As = Asm + buf * AS_BUF;
        const float* Bs = Bsm + buf * BS_BUF;
#pragma unroll
        for (int ks = 0; ks < 4; ks++) {
            int kk = ks * 8;
            uint32_t af[4][4], bf[4][2];
#pragma unroll
            for (int mt = 0; mt < 4; mt++) {
                int r0 = wm + mt * 16;
                af[mt][0] = __float_as_uint(As[(r0 + gid)     * AS_STRIDE + kk + tig]);
                af[mt][1] = __float_as_uint(As[(r0 + gid + 8) * AS_STRIDE + kk + tig]);
                af[mt][2] = __float_as_uint(As[(r0 + gid)     * AS_STRIDE + kk + tig + 4]);
                af[mt][3] = __float_as_uint(As[(r0 + gid + 8) * AS_STRIDE + kk + tig + 4]);
            }
#pragma unroll
            for (int nt = 0; nt < 4; nt++) {
                int c0 = wn + nt * 8;
                bf[nt][0] = __float_as_uint(Bs[(kk + tig)     * BS_STRIDE + c0 + gid]);
                bf[nt][1] = __float_as_uint(Bs[(kk + tig + 4) * BS_STRIDE + c0 + gid]);
            }
#pragma unroll
            for (int mt = 0; mt < 4; mt++)
#pragma unroll
                for (int nt = 0; nt < 4; nt++)
                    asm volatile(
                        "mma.sync.aligned.m16n8k8.row.col.f32.tf32.tf32.f32 "
                        "{%0,%1,%2,%3}, {%4,%5,%6,%7}, {%8,%9}, {%0,%1,%2,%3};"
                        : "+f"(acc[mt][nt][0]), "+f"(acc[mt][nt][1]),
                          "+f"(acc[mt][nt][2]), "+f"(acc[mt][nt][3])
                        : "r"(af[mt][0]), "r"(af[mt][1]), "r"(af[mt][2]), "r"(af[mt][3]),
                          "r"(bf[nt][0]), "r"(bf[nt][1]));
        }
        __syncthreads();   // compute(buf) done before next iter stages into it
    }

#pragma unroll
    for (int mt = 0; mt < 4; mt++) {
#pragma unroll
        for (int nt = 0; nt < 4; nt++) {
            int row0 = bm + wm + mt * 16 + gid;
            int row1 = row0 + 8;
            int col  = bn + wn + nt * 8 + tig * 2;
            float2 v0 = make_float2(acc[mt][nt][0], acc[mt][nt][1]);
            float2 v1 = make_float2(acc[mt][nt][2], acc[mt][nt][3]);
            if (CONV) {
                float2 b2 = *(const float2*)(bias + col);
                float2 r0 = *(const float2*)(resid + row0 * 256 + col);
                float2 r1 = *(const float2*)(resid + row1 * 256 + col);
                v0.x = cvt_tf32(fmaxf(v0.x + b2.x + r0.x, 0.f));
                v0.y = cvt_tf32(fmaxf(v0.y + b2.y + r0.y, 0.f));
                v1.x = cvt_tf32(fmaxf(v1.x + b2.x + r1.x, 0.f));
                v1.y = cvt_tf32(fmaxf(v1.y + b2.y + r1.y, 0.f));
            }
            *(float2*)(C + row0 * 256 + col) = v0;
            *(float2*)(C + row1 * 256 + col) = v1;
        }
    }
}

// ---------------- per-node attention scalars ----------------
__global__ void k_scalars(const float* __restrict__ a_s, const float* __restrict__ a_d) {
    int w = (blockIdx.x * 256 + threadIdx.x) >> 5;
    int lane = threadIdx.x & 31;
    if (w >= NTOT) return;
    const float4* r  = (const float4*)g_hw + w * 64;
    const float4* s4 = (const float4*)a_s;
    const float4* d4 = (const float4*)a_d;
    float4 v0 = r[lane], v1 = r[lane + 32];
    float4 sa = s4[lane], sb = s4[lane + 32];
    float4 da = d4[lane], db = d4[lane + 32];
    float ss = v0.x * sa.x + v0.y * sa.y + v0.z * sa.z + v0.w * sa.w
             + v1.x * sb.x + v1.y * sb.y + v1.z * sb.z + v1.w * sb.w;
    float dd = v0.x * da.x + v0.y * da.y + v0.z * da.z + v0.w * da.w
             + v1.x * db.x + v1.y * db.y + v1.z * db.z + v1.w * db.w;
#pragma unroll
    for (int o = 16; o; o >>= 1) {
        ss += __shfl_xor_sync(0xFFFFFFFFu, ss, o);
        dd += __shfl_xor_sync(0xFFFFFFFFu, dd, o);
    }
    if (lane == 0) { g_s[w] = ss; g_d[w] = dd; }
}

// ---------------- fused edge softmax + aggregate: one warp per dst node ----------------
__global__ __launch_bounds__(256)
void k_gat_edges(const float* __restrict__ bias, int flip) {
    float* hout = flip ? g_h0 : g_h1;
    int w = (blockIdx.x * 256 + threadIdx.x) >> 5;
    int lane = threadIdx.x & 31;
    if (w >= NTOT) return;
    int beg = g_off[w], end = g_off[w + 1];
    float dj = g_d[w];

    float mx = -1e30f;
    for (int i = beg + lane; i < end; i += 32) {
        float e = g_s[g_csrc[i]] + dj;
        e = e > 0.f ? e : 0.2f * e;
        mx = fmaxf(mx, e);
    }
#pragma unroll
    for (int o = 16; o; o >>= 1) mx = fmaxf(mx, __shfl_xor_sync(0xFFFFFFFFu, mx, o));

    float sum = 0.f;
    for (int i = beg + lane; i < end; i += 32) {
        float e = g_s[g_csrc[i]] + dj;
        e = e > 0.f ? e : 0.2f * e;
        sum += __expf(e - mx);
    }
#pragma unroll
    for (int o = 16; o; o >>= 1) sum += __shfl_xor_sync(0xFFFFFFFFu, sum, o);
    float inv = 1.f / sum;

    float4 acc0 = make_float4(0.f, 0.f, 0.f, 0.f);
    float4 acc1 = make_float4(0.f, 0.f, 0.f, 0.f);
    const float4* hw4 = (const float4*)g_hw;
    for (int i = beg; i < end; i++) {
        int s_ = g_csrc[i];                  // uniform across the warp
        float e = g_s[s_] + dj;
        e = e > 0.f ? e : 0.2f * e;
        float wt = __expf(e - mx) * inv;
        const float4* r = hw4 + s_ * 64;
        float4 v0 = r[lane], v1 = r[lane + 32];
        acc0.x += wt * v0.x; acc0.y += wt * v0.y; acc0.z += wt * v0.z; acc0.w += wt * v0.w;
        acc1.x += wt * v1.x; acc1.y += wt * v1.y; acc1.z += wt * v1.z; acc1.w += wt * v1.w;
    }
    const float4* b4 = (const float4*)bias;
    float4 bb0 = b4[lane], bb1 = b4[lane + 32];
    float4 o0, o1;
    o0.x = cvt_tf32(fmaxf(acc0.x + bb0.x, 0.f)); o0.y = cvt_tf32(fmaxf(acc0.y + bb0.y, 0.f));
    o0.z = cvt_tf32(fmaxf(acc0.z + bb0.z, 0.f)); o0.w = cvt_tf32(fmaxf(acc0.w + bb0.w, 0.f));
    o1.x = cvt_tf32(fmaxf(acc1.x + bb1.x, 0.f)); o1.y = cvt_tf32(fmaxf(acc1.y + bb1.y, 0.f));
    o1.z = cvt_tf32(fmaxf(acc1.z + bb1.z, 0.f)); o1.w = cvt_tf32(fmaxf(acc1.w + bb1.w, 0.f));
    ((float4*)hout)[w * 64 + lane]      = o0;
    ((float4*)hout)[w * 64 + 32 + lane] = o1;
}

// ---------------- final conv (position 0 only) + LayerNorm + relu ----------------
__global__ void k_final(const float* __restrict__ tc_w,
                        const float* __restrict__ tc_b, const float* __restrict__ ln_g,
                        const float* __restrict__ ln_b, float* __restrict__ out) {
    __shared__ float h0s[256], h1s[256], red[256];
    int b = blockIdx.x, t = threadIdx.x;
    h0s[t] = g_h1[(b * NN + 0) * 256 + t];
    h1s[t] = g_h1[(b * NN + 1) * 256 + t];
    __syncthreads();
    float v = tc_b[t];
    const float* wr = tc_w + t * 768;
    for (int c = 0; c < 256; c++)
        v += wr[c * 3 + 1] * h0s[c] + wr[c * 3 + 2] * h1s[c];
    red[t] = v;
    __syncthreads();
    for (int o = 128; o; o >>= 1) { if (t < o) red[t] += red[t + o]; __syncthreads(); }
    float mu = red[0] / 256.f;
    __syncthreads();
    red[t] = (v - mu) * (v - mu);
    __syncthreads();
    for (int o = 128; o; o >>= 1) { if (t < o) red[t] += red[t + o]; __syncthreads(); }
    float var = red[0] / 256.f;
    float rs = rsqrtf(var + 1e-5f);
    out[b * 256 + t] = fmaxf((v - mu) * rs * ln_g[t] + ln_b[t], 0.f);
}

// ---------------- launch ----------------
extern "C" void kernel_launch(void* const* d_in, const int* in_sizes, int n_in,
                              void* d_out, int out_size) {
    (void)in_sizes; (void)n_in; (void)out_size;
    const float* x      = (const float*)d_in[0];
    const int*   ei     = (const int*)d_in[1];        // int32 edge_index [2, E]
    const float* tc_w   = (const float*)d_in[2];
    const float* tc_b   = (const float*)d_in[3];
    const float* gat_W  = (const float*)d_in[4];
    const float* gat_as = (const float*)d_in[5];
    const float* gat_ad = (const float*)d_in[6];
    const float* gat_b  = (const float*)d_in[7];
    const float* ln_g   = (const float*)d_in[8];
    const float* ln_b   = (const float*)d_in[9];
    float* out = (float*)d_out;

    cudaFuncSetAttribute(k_mma<-1>, cudaFuncAttributeMaxDynamicSharedMemorySize, MMA_SMEM_BYTES);
    cudaFuncSetAttribute(k_mma<0>,  cudaFuncAttributeMaxDynamicSharedMemorySize, MMA_SMEM_BYTES);
    cudaFuncSetAttribute(k_mma<1>,  cudaFuncAttributeMaxDynamicSharedMemorySize, MMA_SMEM_BYTES);
    cudaFuncSetAttribute(k_mma<2>,  cudaFuncAttributeMaxDynamicSharedMemorySize, MMA_SMEM_BYTES);

    // input prep + CSR build
    k_xpad<<<(NB * 4098 * 64 + 255) / 256, 256>>>(x);
    k_wb<<<768, 256>>>(tc_w);
    k_wl<<<LL * 256, 256>>>(gat_W);
    k_deg_init<<<(NTOT + 255) / 256, 256>>>();
    k_deg_count<<<EE / 256, 256>>>(ei);
    k_scan<<<1, 1024>>>();
    k_fill<<<(EP + 255) / 256, 256>>>(ei);

    // temporal conv (as GEMM M=16384, N=256, K=768) + residual + relu -> g_h0
    k_mma<-1><<<dim3(2, 128), 256, MMA_SMEM_BYTES>>>(0, tc_b, x);

    // 3 GAT layers (ping-pong g_h0 <-> g_h1 via flip flag)
    k_mma<0><<<dim3(2, 128), 256, MMA_SMEM_BYTES>>>(0, nullptr, nullptr);
    k_scalars<<<(NTOT * 32 + 255) / 256, 256>>>(gat_as,       gat_ad);
    k_gat_edges<<<(NTOT * 32 + 255) / 256, 256>>>(gat_b,       0);

    k_mma<1><<<dim3(2, 128), 256, MMA_SMEM_BYTES>>>(1, nullptr, nullptr);
    k_scalars<<<(NTOT * 32 + 255) / 256, 256>>>(gat_as + 256, gat_ad + 256);
    k_gat_edges<<<(NTOT * 32 + 255) / 256, 256>>>(gat_b + 256, 1);

    k_mma<2><<<dim3(2, 128), 256, MMA_SMEM_BYTES>>>(0, nullptr, nullptr);
    k_scalars<<<(NTOT * 32 + 255) / 256, 256>>>(gat_as + 512, gat_ad + 512);
    k_gat_edges<<<(NTOT * 32 + 255) / 256, 256>>>(gat_b + 512, 0);

    // final conv at n=0 + layernorm + relu (reads g_h1)
    k_final<<<NB, 256>>>(tc_w, tc_b, ln_g, ln_b, out);
}